// round 6
// baseline (speedup 1.0000x reference)
#include <cuda_runtime.h>
#include <cuda_bf16.h>
#include <cstdint>
#include <cstddef>

// Problem constants
#define TT   464
#define HH   256
#define BB   64
#define H4   1024              // 4*H
#define MROWS (BB*TT)          // 29696
#define KFLAT (TT*HH)          // 118784
#define NKC   116              // dense split-K chunks (1024 k each)

// ---------------- scratch (static device globals; no allocation) -------------
__device__ float g_Z[(size_t)MROWS * H4];        // x@W + b   (121.6 MB)
__device__ float g_seq[(size_t)BB * KFLAT];      // lstm outputs (30.4 MB)
__device__ float g_part[(size_t)NKC * BB * HH];  // dense partials (7.6 MB)
__device__ float g_dummy[2 * BB * HH];           // fallback for hT/cT

__device__ __forceinline__ float sigmoidf_(float x) {
    return 1.0f / (1.0f + expf(-x));
}

// =============================================================================
// Kernel A: Z[m][n] = sum_k X[m][k]*W[k][n] + bias[n]
// M=29696, K=256, N=1024.  BM=128, BN=64, BK=16, 256 threads, 8x4 per thread.
// =============================================================================
__global__ __launch_bounds__(256) void gemm_xw_kernel(
    const float* __restrict__ X, const float* __restrict__ W,
    const float* __restrict__ bias)
{
    __shared__ float As[16][128];
    __shared__ float Bs[16][64];

    const int tid = threadIdx.x;
    const int tx = tid & 15;          // 0..15  -> 4 cols
    const int ty = tid >> 4;          // 0..15  -> 8 rows
    const int mBase = blockIdx.y * 128;
    const int nBase = blockIdx.x * 64;

    const int lmA = tid >> 1;         // 0..127
    const int lkA = (tid & 1) * 8;    // 0 or 8
    const int lkB = tid >> 4;         // 0..15
    const int lnB = (tid & 15) * 4;

    float acc[8][4];
    #pragma unroll
    for (int i = 0; i < 8; i++)
        #pragma unroll
        for (int j = 0; j < 4; j++) acc[i][j] = 0.0f;

    for (int k0 = 0; k0 < 256; k0 += 16) {
        // load A tile (transposed into SMEM)
        float4 v0 = *reinterpret_cast<const float4*>(&X[(size_t)(mBase + lmA) * 256 + k0 + lkA]);
        float4 v1 = *reinterpret_cast<const float4*>(&X[(size_t)(mBase + lmA) * 256 + k0 + lkA + 4]);
        As[lkA + 0][lmA] = v0.x; As[lkA + 1][lmA] = v0.y;
        As[lkA + 2][lmA] = v0.z; As[lkA + 3][lmA] = v0.w;
        As[lkA + 4][lmA] = v1.x; As[lkA + 5][lmA] = v1.y;
        As[lkA + 6][lmA] = v1.z; As[lkA + 7][lmA] = v1.w;
        // load B tile
        *reinterpret_cast<float4*>(&Bs[lkB][lnB]) =
            *reinterpret_cast<const float4*>(&W[(size_t)(k0 + lkB) * H4 + nBase + lnB]);
        __syncthreads();

        #pragma unroll
        for (int k = 0; k < 16; k++) {
            float4 a0 = *reinterpret_cast<const float4*>(&As[k][ty * 8]);
            float4 a1 = *reinterpret_cast<const float4*>(&As[k][ty * 8 + 4]);
            float4 b0 = *reinterpret_cast<const float4*>(&Bs[k][tx * 4]);
            float ar[8] = {a0.x, a0.y, a0.z, a0.w, a1.x, a1.y, a1.z, a1.w};
            float br[4] = {b0.x, b0.y, b0.z, b0.w};
            #pragma unroll
            for (int i = 0; i < 8; i++)
                #pragma unroll
                for (int j = 0; j < 4; j++)
                    acc[i][j] = fmaf(ar[i], br[j], acc[i][j]);
        }
        __syncthreads();
    }

    float4 bv = *reinterpret_cast<const float4*>(&bias[nBase + tx * 4]);
    #pragma unroll
    for (int i = 0; i < 8; i++) {
        float4 o;
        o.x = acc[i][0] + bv.x; o.y = acc[i][1] + bv.y;
        o.z = acc[i][2] + bv.z; o.w = acc[i][3] + bv.w;
        *reinterpret_cast<float4*>(&g_Z[(size_t)(mBase + ty * 8 + i) * H4 + nBase + tx * 4]) = o;
    }
}

// =============================================================================
// Kernel B: LSTM recurrence.  16 clusters x 8 CTAs, 256 threads each.
// Cluster c handles batches [4c, 4c+4).  CTA rank r holds U columns
// { g*256 + r*32 + d : g in 0..3, d in 0..31 } resident in SMEM (transposed,
// stride 260 floats -> conflict-free LDS.128), and owns h-dims [r*32, r*32+32).
// New h values scattered to all 8 peers via DSMEM, double-buffered,
// one barrier.cluster per step.
// =============================================================================
#define CLSZ 8
#define GBAT 4
#define USTRIDE 260
#define US_FLOATS (128 * USTRIDE)          // 33280
#define HBUF_FLOATS (2 * GBAT * HH)        // 2048
#define ZBUF_FLOATS (4 * 32 * GBAT)        // 512
#define LSTM_SMEM_BYTES ((US_FLOATS + HBUF_FLOATS + ZBUF_FLOATS) * 4)  // 143360

__global__ __cluster_dims__(CLSZ, 1, 1) __launch_bounds__(256, 1)
void lstm_kernel(const float* __restrict__ U,
                 const float* __restrict__ h0, const float* __restrict__ c0,
                 float* __restrict__ outHT, float* __restrict__ outCT)
{
    extern __shared__ float sm[];
    float* Us   = sm;                       // [128][260]
    float* hbuf = sm + US_FLOATS;           // [2][4][256]
    float* zbuf = hbuf + HBUF_FLOATS;       // [4][32][4]

    const int tid = threadIdx.x;
    uint32_t rank_u;
    asm("mov.u32 %0, %%cluster_ctarank;" : "=r"(rank_u));
    const int r   = (int)rank_u;
    const int cid = blockIdx.x / CLSZ;
    const int gb0 = cid * GBAT;

    // ---- stage U slice into SMEM, transposed [col][k] ----
    for (int idx = tid; idx < 256 * 128; idx += 256) {
        int k = idx >> 7;
        int l = idx & 127;
        int gcol = (l >> 5) * 256 + r * 32 + (l & 31);
        Us[l * USTRIDE + k] = U[(size_t)k * H4 + gcol];
    }
    // ---- h0 into hbuf parity 0 ----
    for (int idx = tid; idx < GBAT * HH; idx += 256) {
        int b = idx >> 8;
        int k = idx & 255;
        hbuf[b * HH + k] = h0[(size_t)(gb0 + b) * HH + k];
    }
    // ---- c state in registers (threads 0..127 own (dim, batch)) ----
    const int bc = tid >> 5;   // valid for tid<128: 0..3
    const int dc = tid & 31;
    float creg = 0.0f;
    if (tid < 128) creg = c0[(size_t)(gb0 + bc) * HH + r * 32 + dc];

    // dot-phase mapping
    const int l    = tid & 127;
    const int bp   = tid >> 7;       // batch pair: 0 -> {0,1}, 1 -> {2,3}
    const int gate = l >> 5;
    const int dl   = l & 31;
    const int gcol = gate * 256 + r * 32 + dl;

    const uint32_t hb_base = (uint32_t)__cvta_generic_to_shared(hbuf);

    asm volatile("barrier.cluster.arrive.aligned;\n" ::: "memory");
    asm volatile("barrier.cluster.wait.aligned;\n" ::: "memory");

    for (int step = 0; step < TT; step++) {
        const int p = step & 1;
        // prefetch x@W+b contributions (DRAM/L2; consumed ~2000 cyc later)
        float z0 = g_Z[((size_t)(gb0 + bp * 2 + 0) * TT + step) * H4 + gcol];
        float z1 = g_Z[((size_t)(gb0 + bp * 2 + 1) * TT + step) * H4 + gcol];

        const float4* u4 = reinterpret_cast<const float4*>(Us + l * USTRIDE);
        const float4* hx = reinterpret_cast<const float4*>(hbuf + p * (GBAT * HH) + (bp * 2 + 0) * HH);
        const float4* hy = reinterpret_cast<const float4*>(hbuf + p * (GBAT * HH) + (bp * 2 + 1) * HH);

        float a0 = 0.0f, a1 = 0.0f;
        #pragma unroll 8
        for (int kk = 0; kk < 64; kk++) {
            float4 u = u4[kk];
            float4 x = hx[kk];
            float4 y = hy[kk];
            a0 = fmaf(u.x, x.x, a0); a0 = fmaf(u.y, x.y, a0);
            a0 = fmaf(u.z, x.z, a0); a0 = fmaf(u.w, x.w, a0);
            a1 = fmaf(u.x, y.x, a1); a1 = fmaf(u.y, y.y, a1);
            a1 = fmaf(u.z, y.z, a1); a1 = fmaf(u.w, y.w, a1);
        }
        zbuf[(gate * 32 + dl) * 4 + bp * 2 + 0] = z0 + a0;
        zbuf[(gate * 32 + dl) * 4 + bp * 2 + 1] = z1 + a1;
        __syncthreads();

        if (tid < 128) {
            float zi = zbuf[(0 * 32 + dc) * 4 + bc];
            float zf = zbuf[(1 * 32 + dc) * 4 + bc];
            float zg = zbuf[(2 * 32 + dc) * 4 + bc];
            float zo = zbuf[(3 * 32 + dc) * 4 + bc];
            float ig = sigmoidf_(zi);
            float fg = sigmoidf_(zf);
            creg = fg * creg + ig * fmaxf(zg, 0.0f);
            float hval = sigmoidf_(zo) * fmaxf(creg, 0.0f);

            g_seq[(size_t)(gb0 + bc) * KFLAT + step * HH + r * 32 + dc] = hval;

            uint32_t addr = hb_base +
                (uint32_t)(((p ^ 1) * (GBAT * HH) + bc * HH + r * 32 + dc) * 4);
            #pragma unroll
            for (int rk = 0; rk < CLSZ; rk++) {
                uint32_t ra;
                asm volatile("mapa.shared::cluster.u32 %0, %1, %2;"
                             : "=r"(ra) : "r"(addr), "r"(rk));
                asm volatile("st.shared::cluster.f32 [%0], %1;"
                             :: "r"(ra), "f"(hval) : "memory");
            }
            if (step == TT - 1) {
                outHT[(size_t)(gb0 + bc) * HH + r * 32 + dc] = hval;
                outCT[(size_t)(gb0 + bc) * HH + r * 32 + dc] = creg;
            }
        }
        asm volatile("barrier.cluster.arrive.aligned;\n" ::: "memory");
        asm volatile("barrier.cluster.wait.aligned;\n" ::: "memory");
    }
}

// =============================================================================
// Kernel C: dense split-K partials.
// part[kc][b][n] = sum_{k in chunk kc} seq[b][k] * Wd[k][n]
// M=64, N=256 (4 tiles of 64), K=118784 (116 chunks of 1024).
// BM=64, BN=64, BK=16, 256 threads, 4x4 per thread.
// =============================================================================
__global__ __launch_bounds__(256) void gemm_dense_kernel(const float* __restrict__ Wd)
{
    __shared__ float As[16][64];
    __shared__ float Bs[16][64];

    const int tid = threadIdx.x;
    const int tx = tid & 15;
    const int ty = tid >> 4;
    const int nBase = blockIdx.x * 64;
    const int kc = blockIdx.y;
    const int kBase = kc * 1024;

    const int lmA = tid >> 2;          // 0..63
    const int lkA = (tid & 3) * 4;     // 0,4,8,12
    const int lkB = tid >> 4;          // 0..15
    const int lnB = (tid & 15) * 4;

    float acc[4][4];
    #pragma unroll
    for (int i = 0; i < 4; i++)
        #pragma unroll
        for (int j = 0; j < 4; j++) acc[i][j] = 0.0f;

    for (int it = 0; it < 64; it++) {
        const int k0 = kBase + it * 16;
        float4 av = *reinterpret_cast<const float4*>(&g_seq[(size_t)lmA * KFLAT + k0 + lkA]);
        As[lkA + 0][lmA] = av.x; As[lkA + 1][lmA] = av.y;
        As[lkA + 2][lmA] = av.z; As[lkA + 3][lmA] = av.w;
        *reinterpret_cast<float4*>(&Bs[lkB][lnB]) =
            *reinterpret_cast<const float4*>(&Wd[(size_t)(k0 + lkB) * HH + nBase + lnB]);
        __syncthreads();

        #pragma unroll
        for (int k = 0; k < 16; k++) {
            float4 a = *reinterpret_cast<const float4*>(&As[k][ty * 4]);
            float4 b = *reinterpret_cast<const float4*>(&Bs[k][tx * 4]);
            float ar[4] = {a.x, a.y, a.z, a.w};
            float br[4] = {b.x, b.y, b.z, b.w};
            #pragma unroll
            for (int i = 0; i < 4; i++)
                #pragma unroll
                for (int j = 0; j < 4; j++)
                    acc[i][j] = fmaf(ar[i], br[j], acc[i][j]);
        }
        __syncthreads();
    }

    #pragma unroll
    for (int i = 0; i < 4; i++) {
        float4 o;
        o.x = acc[i][0]; o.y = acc[i][1]; o.z = acc[i][2]; o.w = acc[i][3];
        *reinterpret_cast<float4*>(
            &g_part[((size_t)kc * 64 + ty * 4 + i) * HH + nBase + tx * 4]) = o;
    }
}

// Final reduce + bias + relu -> core_output
__global__ __launch_bounds__(256) void reduce_dense_kernel(
    const float* __restrict__ bd, float* __restrict__ outCore)
{
    const int b = blockIdx.x;
    const int n = threadIdx.x;
    float s = bd[n];
    #pragma unroll 4
    for (int kc = 0; kc < NKC; kc++)
        s += g_part[((size_t)kc * 64 + b) * HH + n];
    outCore[(size_t)b * HH + n] = fmaxf(s, 0.0f);
}

// =============================================================================
extern "C" void kernel_launch(void* const* d_in, const int* in_sizes, int n_in,
                              void* d_out, int out_size)
{
    const float* X  = (const float*)d_in[0];  // [64,464,256]
    const float* h0 = (const float*)d_in[1];  // [64,256]
    const float* c0 = (const float*)d_in[2];  // [64,256]
    const float* W  = (const float*)d_in[3];  // [256,1024]
    const float* U  = (const float*)d_in[4];  // [256,1024]
    const float* bb = (const float*)d_in[5];  // [1024]
    const float* Wd = (const float*)d_in[6];  // [118784,256]
    const float* bd = (const float*)d_in[7];  // [256]
    float* out = (float*)d_out;

    float* outCore = out;
    float* outHT;
    float* outCT;
    if (out_size >= 3 * BB * HH) {
        outHT = out + BB * HH;
        outCT = out + 2 * BB * HH;
    } else {
        // output is only core_output; park states in scratch
        float* dummy = nullptr;
        cudaGetSymbolAddress((void**)&dummy, g_dummy);
        outHT = dummy;
        outCT = dummy + BB * HH;
    }

    // allow 140 KB dynamic SMEM for the recurrence kernel
    cudaFuncSetAttribute(lstm_kernel,
                         cudaFuncAttributeMaxDynamicSharedMemorySize,
                         LSTM_SMEM_BYTES);

    // 1) Z = X@W + b
    gemm_xw_kernel<<<dim3(H4 / 64, MROWS / 128), 256>>>(X, W, bb);

    // 2) recurrence (16 clusters x 8 CTAs)
    lstm_kernel<<<128, 256, LSTM_SMEM_BYTES>>>(U, h0, c0, outHT, outCT);

    // 3) dense split-K + reduce
    gemm_dense_kernel<<<dim3(HH / 64, NKC), 256>>>(Wd);
    reduce_dense_kernel<<<BB, 256>>>(bd, outCore);
}